// round 1
// baseline (speedup 1.0000x reference)
#include <cuda_runtime.h>
#include <math.h>

// ---------------- problem constants ----------------
#define D_MODEL 768
#define D_HID   3072
#define NE      8
#define TOPK    2
#define NTOK    2048
#define NASSIGN (NTOK*TOPK)          // 4096

// ---------------- GEMM tiling ----------------
#define BM 128
#define BN 128
#define BK 8
#define PAD 4
#define MAXM     (NASSIGN + NE*BM)   // 5120 (per-expert padding to BM)
#define MAXTILES (NASSIGN/BM + NE)   // 40

// ---------------- scratch (device globals; no allocation allowed) ----------------
__device__ int   g_counts[NE];
__device__ int   g_cursor[NE];
__device__ int   g_tile_e[MAXTILES];
__device__ int   g_tile_m0[MAXTILES];
__device__ int   g_ntiles;
__device__ int   g_expert_of[NASSIGN];
__device__ float g_w_of[NASSIGN];
__device__ int   g_slot_of[NASSIGN];
__device__ int   g_tok[MAXM];
__device__ float g_wt[MAXM];
__device__ float g_h[(size_t)MAXM * D_HID];     // ~63 MB
__device__ float g_y[(size_t)MAXM * D_MODEL];   // ~16 MB

__device__ __forceinline__ float gelu_erf(float v) {
    return 0.5f * v * (1.0f + erff(v * 0.7071067811865476f));
}

// ---------------- init: zero counters ----------------
__global__ void init_kernel() {
    if (threadIdx.x < NE) g_counts[threadIdx.x] = 0;
}

// ---------------- router: logits -> softmax -> top2 -> normalized weights ----------------
// one warp per token
__global__ __launch_bounds__(256) void router_kernel(const float* __restrict__ x,
                                                     const float* __restrict__ gate_w) {
    int warp = (blockIdx.x * blockDim.x + threadIdx.x) >> 5;
    int lane = threadIdx.x & 31;
    if (warp >= NTOK) return;
    const float* xr = x + (size_t)warp * D_MODEL;

    float acc[NE];
#pragma unroll
    for (int e = 0; e < NE; e++) acc[e] = 0.f;
    for (int d = lane; d < D_MODEL; d += 32) {
        float xv = xr[d];
        const float4* gw = (const float4*)(gate_w + (size_t)d * NE);
        float4 a = gw[0], b = gw[1];
        acc[0] = fmaf(xv, a.x, acc[0]); acc[1] = fmaf(xv, a.y, acc[1]);
        acc[2] = fmaf(xv, a.z, acc[2]); acc[3] = fmaf(xv, a.w, acc[3]);
        acc[4] = fmaf(xv, b.x, acc[4]); acc[5] = fmaf(xv, b.y, acc[5]);
        acc[6] = fmaf(xv, b.z, acc[6]); acc[7] = fmaf(xv, b.w, acc[7]);
    }
#pragma unroll
    for (int e = 0; e < NE; e++) {
#pragma unroll
        for (int o = 16; o > 0; o >>= 1)
            acc[e] += __shfl_xor_sync(0xffffffffu, acc[e], o);
    }
    if (lane == 0) {
        float mx = acc[0];
#pragma unroll
        for (int e = 1; e < NE; e++) mx = fmaxf(mx, acc[e]);
        float p[NE]; float s = 0.f;
#pragma unroll
        for (int e = 0; e < NE; e++) { p[e] = expf(acc[e] - mx); s += p[e]; }
        float inv = 1.0f / s;
#pragma unroll
        for (int e = 0; e < NE; e++) p[e] *= inv;
        // top-2 (ties -> lowest index, matching jax top_k)
        int i0 = 0;
#pragma unroll
        for (int e = 1; e < NE; e++) if (p[e] > p[i0]) i0 = e;
        int i1 = (i0 == 0) ? 1 : 0;
#pragma unroll
        for (int e = 0; e < NE; e++) if (e != i0 && p[e] > p[i1]) i1 = e;
        float w0 = p[i0], w1 = p[i1];
        float isw = 1.0f / (w0 + w1);
        w0 *= isw; w1 *= isw;
        g_expert_of[warp * 2 + 0] = i0;
        g_expert_of[warp * 2 + 1] = i1;
        g_w_of[warp * 2 + 0] = w0;
        g_w_of[warp * 2 + 1] = w1;
        atomicAdd(&g_counts[i0], 1);
        atomicAdd(&g_counts[i1], 1);
    }
}

// ---------------- setup: tile-aligned group offsets + tile map + clear slots ----------------
__global__ void setup_kernel() {
    if (threadIdx.x == 0) {
        int off = 0, t = 0;
        for (int e = 0; e < NE; e++) {
            g_cursor[e] = off;
            int nt = (g_counts[e] + BM - 1) / BM;
            for (int i = 0; i < nt; i++) { g_tile_e[t] = e; g_tile_m0[t] = off + i * BM; t++; }
            off += nt * BM;
        }
        g_ntiles = t;
    }
    __syncthreads();
    for (int i = threadIdx.x; i < MAXM; i += blockDim.x) { g_tok[i] = -1; g_wt[i] = 0.f; }
}

// ---------------- scatter assignments into slots ----------------
__global__ void scatter_kernel() {
    int idx = blockIdx.x * blockDim.x + threadIdx.x;
    if (idx >= NASSIGN) return;
    int e = g_expert_of[idx];
    int slot = atomicAdd(&g_cursor[e], 1);
    g_tok[slot] = idx >> 1;
    g_wt[slot] = g_w_of[idx];
    g_slot_of[idx] = slot;
}

// ---------------- grouped GEMM1: h = gelu(X_g @ w1[e] + b1[e]) ----------------
__global__ __launch_bounds__(256) void gemm1_kernel(const float* __restrict__ x,
                                                    const float* __restrict__ w1,
                                                    const float* __restrict__ b1) {
    int tile = blockIdx.y;
    if (tile >= g_ntiles) return;
    int e  = g_tile_e[tile];
    int m0 = g_tile_m0[tile];
    int n0 = blockIdx.x * BN;
    const float* Bmat = w1 + (size_t)e * D_MODEL * D_HID;   // [768][3072]

    __shared__ float As[BK][BM + PAD];
    __shared__ float Bs[BK][BN];

    int tid = threadIdx.x;
    int tx = tid & 15, ty = tid >> 4;

    float acc[8][8];
#pragma unroll
    for (int i = 0; i < 8; i++)
#pragma unroll
        for (int j = 0; j < 8; j++) acc[i][j] = 0.f;

    int arow = tid >> 1, ak = (tid & 1) * 4;
    int tokA = g_tok[m0 + arow];
    const float* aptr = (tokA >= 0) ? (x + (size_t)tokA * D_MODEL) : (const float*)0;
    int bkr = tid >> 5, bn = (tid & 31) * 4;

    for (int k0 = 0; k0 < D_MODEL; k0 += BK) {
        float4 av = aptr ? *(const float4*)(aptr + k0 + ak)
                         : make_float4(0.f, 0.f, 0.f, 0.f);
        As[ak + 0][arow] = av.x; As[ak + 1][arow] = av.y;
        As[ak + 2][arow] = av.z; As[ak + 3][arow] = av.w;
        *(float4*)&Bs[bkr][bn] =
            *(const float4*)(Bmat + (size_t)(k0 + bkr) * D_HID + n0 + bn);
        __syncthreads();
#pragma unroll
        for (int k = 0; k < BK; k++) {
            float a[8], b[8];
            *(float4*)&a[0] = *(const float4*)&As[k][ty * 4];
            *(float4*)&a[4] = *(const float4*)&As[k][ty * 4 + 64];
            *(float4*)&b[0] = *(const float4*)&Bs[k][tx * 4];
            *(float4*)&b[4] = *(const float4*)&Bs[k][tx * 4 + 64];
#pragma unroll
            for (int i = 0; i < 8; i++)
#pragma unroll
                for (int j = 0; j < 8; j++)
                    acc[i][j] = fmaf(a[i], b[j], acc[i][j]);
        }
        __syncthreads();
    }

    const float* b1e = b1 + (size_t)e * D_HID + n0;
#pragma unroll
    for (int i = 0; i < 8; i++) {
        int m = m0 + ty * 4 + ((i < 4) ? i : (60 + i));
        float* hrow = g_h + (size_t)m * D_HID + n0;
#pragma unroll
        for (int jh = 0; jh < 2; jh++) {
            int nb = tx * 4 + jh * 64;
            float4 bb = *(const float4*)(b1e + nb);
            float4 r;
            r.x = gelu_erf(acc[i][jh * 4 + 0] + bb.x);
            r.y = gelu_erf(acc[i][jh * 4 + 1] + bb.y);
            r.z = gelu_erf(acc[i][jh * 4 + 2] + bb.z);
            r.w = gelu_erf(acc[i][jh * 4 + 3] + bb.w);
            *(float4*)(hrow + nb) = r;
        }
    }
}

// ---------------- grouped GEMM2: y = wt * (H_g @ w2[e] + b2[e]) ----------------
__global__ __launch_bounds__(256) void gemm2_kernel(const float* __restrict__ w2,
                                                    const float* __restrict__ b2) {
    int tile = blockIdx.y;
    if (tile >= g_ntiles) return;
    int e  = g_tile_e[tile];
    int m0 = g_tile_m0[tile];
    int n0 = blockIdx.x * BN;
    const float* Bmat = w2 + (size_t)e * D_HID * D_MODEL;   // [3072][768]

    __shared__ float As[BK][BM + PAD];
    __shared__ float Bs[BK][BN];

    int tid = threadIdx.x;
    int tx = tid & 15, ty = tid >> 4;

    float acc[8][8];
#pragma unroll
    for (int i = 0; i < 8; i++)
#pragma unroll
        for (int j = 0; j < 8; j++) acc[i][j] = 0.f;

    int arow = tid >> 1, ak = (tid & 1) * 4;
    const float* aptr = g_h + (size_t)(m0 + arow) * D_HID;
    int bkr = tid >> 5, bn = (tid & 31) * 4;

    for (int k0 = 0; k0 < D_HID; k0 += BK) {
        float4 av = *(const float4*)(aptr + k0 + ak);
        As[ak + 0][arow] = av.x; As[ak + 1][arow] = av.y;
        As[ak + 2][arow] = av.z; As[ak + 3][arow] = av.w;
        *(float4*)&Bs[bkr][bn] =
            *(const float4*)(Bmat + (size_t)(k0 + bkr) * D_MODEL + n0 + bn);
        __syncthreads();
#pragma unroll
        for (int k = 0; k < BK; k++) {
            float a[8], b[8];
            *(float4*)&a[0] = *(const float4*)&As[k][ty * 4];
            *(float4*)&a[4] = *(const float4*)&As[k][ty * 4 + 64];
            *(float4*)&b[0] = *(const float4*)&Bs[k][tx * 4];
            *(float4*)&b[4] = *(const float4*)&Bs[k][tx * 4 + 64];
#pragma unroll
            for (int i = 0; i < 8; i++)
#pragma unroll
                for (int j = 0; j < 8; j++)
                    acc[i][j] = fmaf(a[i], b[j], acc[i][j]);
        }
        __syncthreads();
    }

    const float* b2e = b2 + (size_t)e * D_MODEL + n0;
#pragma unroll
    for (int i = 0; i < 8; i++) {
        int m = m0 + ty * 4 + ((i < 4) ? i : (60 + i));
        float wt = g_wt[m];
        float* yrow = g_y + (size_t)m * D_MODEL + n0;
#pragma unroll
        for (int jh = 0; jh < 2; jh++) {
            int nb = tx * 4 + jh * 64;
            float4 bb = *(const float4*)(b2e + nb);
            float4 r;
            r.x = wt * (acc[i][jh * 4 + 0] + bb.x);
            r.y = wt * (acc[i][jh * 4 + 1] + bb.y);
            r.z = wt * (acc[i][jh * 4 + 2] + bb.z);
            r.w = wt * (acc[i][jh * 4 + 3] + bb.w);
            *(float4*)(yrow + nb) = r;
        }
    }
}

// ---------------- combine: out[n] = y[slot0(n)] + y[slot1(n)] ----------------
__global__ __launch_bounds__(256) void combine_kernel(float* __restrict__ out) {
    int idx = blockIdx.x * blockDim.x + threadIdx.x;   // over NTOK * D_MODEL/4
    if (idx >= NTOK * (D_MODEL / 4)) return;
    int n  = idx / (D_MODEL / 4);
    int d4 = idx % (D_MODEL / 4);
    int s0 = g_slot_of[n * 2 + 0];
    int s1 = g_slot_of[n * 2 + 1];
    float4 a = *(const float4*)(g_y + (size_t)s0 * D_MODEL + d4 * 4);
    float4 b = *(const float4*)(g_y + (size_t)s1 * D_MODEL + d4 * 4);
    float4 r = make_float4(a.x + b.x, a.y + b.y, a.z + b.z, a.w + b.w);
    *(float4*)(out + (size_t)idx * 4) = r;
}

// ---------------- launch ----------------
extern "C" void kernel_launch(void* const* d_in, const int* in_sizes, int n_in,
                              void* d_out, int out_size) {
    const float* x      = (const float*)d_in[0];
    const float* gate_w = (const float*)d_in[1];
    const float* w1     = (const float*)d_in[2];
    const float* b1     = (const float*)d_in[3];
    const float* w2     = (const float*)d_in[4];
    const float* b2     = (const float*)d_in[5];
    float* out = (float*)d_out;

    init_kernel<<<1, 32>>>();
    router_kernel<<<NTOK / 8, 256>>>(x, gate_w);
    setup_kernel<<<1, 256>>>();
    scatter_kernel<<<NASSIGN / 256, 256>>>();
    gemm1_kernel<<<dim3(D_HID / BN, MAXTILES), 256>>>(x, w1, b1);
    gemm2_kernel<<<dim3(D_MODEL / BN, MAXTILES), 256>>>(w2, b2);
    combine_kernel<<<(NTOK * (D_MODEL / 4) + 255) / 256, 256>>>(out);
}

// round 3
// speedup vs baseline: 2.5282x; 2.5282x over previous
#include <cuda_runtime.h>
#include <cuda_bf16.h>
#include <math.h>
#include <stdint.h>

// ---------------- problem constants ----------------
#define D_MODEL 768
#define D_HID   3072
#define NE      8
#define NTOK    2048
#define NASSIGN (NTOK*2)             // 4096
#define BM 128
#define BN 128
#define BK 32
#define MAXM     (NASSIGN + NE*BM)   // 5120
#define MAXTILES (NASSIGN/BM + NE)   // 40

// ---------------- smem layout (bytes, per buffer) ----------------
#define PA 80                        // A row pitch (32 bf16 = 64B data, odd chunk count)
#define PB 272                       // B row pitch (128 bf16 = 256B data, odd chunk count)
#define A_HI 0
#define A_LO (128*PA)                // 10240
#define B_HI (2*128*PA)              // 20480
#define B_LO (2*128*PA + 32*PB)      // 29184
#define BUFSZ (2*128*PA + 2*32*PB)   // 37888
#define SMEM_DYN (2*BUFSZ)           // 75776

// ---------------- scratch ----------------
__device__ int   g_counts[NE];
__device__ int   g_cursor[NE];
__device__ int   g_tile_e[MAXTILES];
__device__ int   g_tile_m0[MAXTILES];
__device__ int   g_ntiles;
__device__ int   g_expert_of[NASSIGN];
__device__ float g_w_of[NASSIGN];
__device__ int   g_slot_of[NASSIGN];
__device__ int   g_tok[MAXM];
__device__ float g_wt[MAXM];
__device__ float g_h[(size_t)MAXM * D_HID];
__device__ float g_y[(size_t)MAXM * D_MODEL];

// ---------------- helpers ----------------
__device__ __forceinline__ uint32_t smem_u32(const void* p) {
    uint32_t a;
    asm("{ .reg .u64 t; cvta.to.shared.u64 t, %1; cvt.u32.u64 %0, t; }" : "=r"(a) : "l"(p));
    return a;
}
__device__ __forceinline__ void sts64(uint32_t addr, uint32_t x, uint32_t y) {
    asm volatile("st.shared.v2.b32 [%0], {%1, %2};" :: "r"(addr), "r"(x), "r"(y) : "memory");
}
__device__ __forceinline__ void ldsm4(uint32_t* r, uint32_t addr) {
    asm volatile("ldmatrix.sync.aligned.m8n8.x4.shared.b16 {%0,%1,%2,%3}, [%4];"
                 : "=r"(r[0]), "=r"(r[1]), "=r"(r[2]), "=r"(r[3]) : "r"(addr));
}
__device__ __forceinline__ void ldsm4t(uint32_t* r, uint32_t addr) {
    asm volatile("ldmatrix.sync.aligned.m8n8.x4.trans.shared.b16 {%0,%1,%2,%3}, [%4];"
                 : "=r"(r[0]), "=r"(r[1]), "=r"(r[2]), "=r"(r[3]) : "r"(addr));
}
__device__ __forceinline__ void mma16816(float* d, const uint32_t* a, const uint32_t* b) {
    asm volatile("mma.sync.aligned.m16n8k16.row.col.f32.bf16.bf16.f32 "
                 "{%0,%1,%2,%3}, {%4,%5,%6,%7}, {%8,%9}, {%0,%1,%2,%3};"
                 : "+f"(d[0]), "+f"(d[1]), "+f"(d[2]), "+f"(d[3])
                 : "r"(a[0]), "r"(a[1]), "r"(a[2]), "r"(a[3]), "r"(b[0]), "r"(b[1]));
}
__device__ __forceinline__ float gelu_erf(float v) {
    return 0.5f * v * (1.0f + erff(v * 0.7071067811865476f));
}
__device__ __forceinline__ uint32_t pk_hi(float a, float b, float& ra, float& rb) {
    __nv_bfloat162 h = __floats2bfloat162_rn(a, b);
    float2 f = __bfloat1622float2(h);
    ra = a - f.x; rb = b - f.y;
    uint32_t u; memcpy(&u, &h, 4); return u;
}
__device__ __forceinline__ uint32_t pk(float a, float b) {
    __nv_bfloat162 h = __floats2bfloat162_rn(a, b);
    uint32_t u; memcpy(&u, &h, 4); return u;
}

// ---------------- router path ----------------
__global__ void init_kernel() {
    if (threadIdx.x < NE) g_counts[threadIdx.x] = 0;
}

__global__ __launch_bounds__(256) void router_kernel(const float* __restrict__ x,
                                                     const float* __restrict__ gate_w) {
    int warp = (blockIdx.x * blockDim.x + threadIdx.x) >> 5;
    int lane = threadIdx.x & 31;
    if (warp >= NTOK) return;
    const float* xr = x + (size_t)warp * D_MODEL;
    float acc[NE];
#pragma unroll
    for (int e = 0; e < NE; e++) acc[e] = 0.f;
    for (int d = lane; d < D_MODEL; d += 32) {
        float xv = xr[d];
        const float4* gw = (const float4*)(gate_w + (size_t)d * NE);
        float4 a = gw[0], b = gw[1];
        acc[0] = fmaf(xv, a.x, acc[0]); acc[1] = fmaf(xv, a.y, acc[1]);
        acc[2] = fmaf(xv, a.z, acc[2]); acc[3] = fmaf(xv, a.w, acc[3]);
        acc[4] = fmaf(xv, b.x, acc[4]); acc[5] = fmaf(xv, b.y, acc[5]);
        acc[6] = fmaf(xv, b.z, acc[6]); acc[7] = fmaf(xv, b.w, acc[7]);
    }
#pragma unroll
    for (int e = 0; e < NE; e++)
#pragma unroll
        for (int o = 16; o > 0; o >>= 1)
            acc[e] += __shfl_xor_sync(0xffffffffu, acc[e], o);
    if (lane == 0) {
        float mx = acc[0];
#pragma unroll
        for (int e = 1; e < NE; e++) mx = fmaxf(mx, acc[e]);
        float p[NE]; float s = 0.f;
#pragma unroll
        for (int e = 0; e < NE; e++) { p[e] = expf(acc[e] - mx); s += p[e]; }
        float inv = 1.0f / s;
#pragma unroll
        for (int e = 0; e < NE; e++) p[e] *= inv;
        int i0 = 0;
#pragma unroll
        for (int e = 1; e < NE; e++) if (p[e] > p[i0]) i0 = e;
        int i1 = (i0 == 0) ? 1 : 0;
#pragma unroll
        for (int e = 0; e < NE; e++) if (e != i0 && p[e] > p[i1]) i1 = e;
        float w0 = p[i0], w1 = p[i1];
        float isw = 1.0f / (w0 + w1);
        g_expert_of[warp * 2 + 0] = i0;
        g_expert_of[warp * 2 + 1] = i1;
        g_w_of[warp * 2 + 0] = w0 * isw;
        g_w_of[warp * 2 + 1] = w1 * isw;
        atomicAdd(&g_counts[i0], 1);
        atomicAdd(&g_counts[i1], 1);
    }
}

__global__ void setup_kernel() {
    if (threadIdx.x == 0) {
        int off = 0, t = 0;
        for (int e = 0; e < NE; e++) {
            g_cursor[e] = off;
            int nt = (g_counts[e] + BM - 1) / BM;
            for (int i = 0; i < nt; i++) { g_tile_e[t] = e; g_tile_m0[t] = off + i * BM; t++; }
            off += nt * BM;
        }
        g_ntiles = t;
    }
    __syncthreads();
    for (int i = threadIdx.x; i < MAXM; i += blockDim.x) { g_tok[i] = -1; g_wt[i] = 0.f; }
}

__global__ void scatter_kernel() {
    int idx = blockIdx.x * blockDim.x + threadIdx.x;
    if (idx >= NASSIGN) return;
    int e = g_expert_of[idx];
    int slot = atomicAdd(&g_cursor[e], 1);
    g_tok[slot] = idx >> 1;
    g_wt[slot] = g_w_of[idx];
    g_slot_of[idx] = slot;
}

// ---------------- grouped GEMM via mma.sync (bf16 3-term split) ----------------
template<bool G1, int KTOT, int NWID>
__global__ __launch_bounds__(256) void moe_gemm(const float* __restrict__ Aext,
                                                const float* __restrict__ Wsrc,
                                                const float* __restrict__ bias) {
    int tile = blockIdx.y;
    if (tile >= g_ntiles) return;
    int e  = g_tile_e[tile];
    int m0 = g_tile_m0[tile];
    int n0 = blockIdx.x * BN;
    const float* W = Wsrc + (size_t)e * KTOT * NWID;
    float* Out = G1 ? g_h : g_y;

    extern __shared__ char smem[];
    uint32_t sb = smem_u32(smem);
    __shared__ int s_tok[BM];

    int tid = threadIdx.x, lane = tid & 31, wid = tid >> 5;
    int wm = wid >> 2, wn = wid & 3;

    if (G1 && tid < BM) s_tok[tid] = g_tok[m0 + tid];
    __syncthreads();

    // copy mapping: A: 1024 float4 -> 4/thread; B: 1024 float4 -> 4/thread
    const int aq = tid & 7, ar0 = tid >> 3;      // A: float4 col aq, rows ar0 + 32r
    const int bq = tid & 31, bk0 = tid >> 5;     // B: float4 col bq, k-rows bk0 + 8r

    int atok[4];
    const float* aRow[4];
    if (G1) {
#pragma unroll
        for (int r = 0; r < 4; r++) {
            atok[r] = s_tok[ar0 + 32 * r];
            aRow[r] = Aext + (size_t)((atok[r] < 0) ? 0 : atok[r]) * KTOT;
        }
    } else {
#pragma unroll
        for (int r = 0; r < 4; r++) {
            atok[r] = 0;
            aRow[r] = g_h + (size_t)(m0 + ar0 + 32 * r) * KTOT;
        }
    }

    float4 pa[4], pb[4];
    const int NCH = KTOT / BK;

    auto load_chunk = [&](int kc) {
#pragma unroll
        for (int r = 0; r < 4; r++) {
            if (G1 && atok[r] < 0) pa[r] = make_float4(0.f, 0.f, 0.f, 0.f);
            else                   pa[r] = *(const float4*)(aRow[r] + kc * BK + aq * 4);
        }
#pragma unroll
        for (int r = 0; r < 4; r++)
            pb[r] = *(const float4*)(W + (size_t)(kc * BK + bk0 + 8 * r) * NWID + n0 + bq * 4);
    };
    auto store_chunk = [&](int buf) {
        uint32_t base = sb + buf * BUFSZ;
#pragma unroll
        for (int r = 0; r < 4; r++) {
            float rx, ry, rz, rw;
            uint32_t h0 = pk_hi(pa[r].x, pa[r].y, rx, ry);
            uint32_t h1 = pk_hi(pa[r].z, pa[r].w, rz, rw);
            uint32_t l0 = pk(rx, ry), l1 = pk(rz, rw);
            uint32_t off = (uint32_t)(ar0 + 32 * r) * PA + aq * 8;
            sts64(base + A_HI + off, h0, h1);
            sts64(base + A_LO + off, l0, l1);
        }
#pragma unroll
        for (int r = 0; r < 4; r++) {
            float rx, ry, rz, rw;
            uint32_t h0 = pk_hi(pb[r].x, pb[r].y, rx, ry);
            uint32_t h1 = pk_hi(pb[r].z, pb[r].w, rz, rw);
            uint32_t l0 = pk(rx, ry), l1 = pk(rz, rw);
            uint32_t off = (uint32_t)(bk0 + 8 * r) * PB + bq * 8;
            sts64(base + B_HI + off, h0, h1);
            sts64(base + B_LO + off, l0, l1);
        }
    };

    float acc[4][4][4];
#pragma unroll
    for (int i = 0; i < 4; i++)
#pragma unroll
        for (int j = 0; j < 4; j++)
#pragma unroll
            for (int k = 0; k < 4; k++) acc[i][j][k] = 0.f;

    load_chunk(0);
    store_chunk(0);
    __syncthreads();

#pragma unroll 1
    for (int kc = 0; kc < NCH; kc++) {
        bool more = (kc + 1 < NCH);
        if (more) load_chunk(kc + 1);

        uint32_t base = sb + (kc & 1) * BUFSZ;
#pragma unroll
        for (int kf = 0; kf < 2; kf++) {
            uint32_t ah[4][4], al[4][4], bh[4][2], bl[4][2];
#pragma unroll
            for (int mf = 0; mf < 4; mf++) {
                uint32_t arow = wm * 64 + mf * 16 + (lane & 15);
                uint32_t aoff = arow * PA + kf * 32 + ((lane >> 4) << 4);
                ldsm4(ah[mf], base + A_HI + aoff);
                ldsm4(al[mf], base + A_LO + aoff);
            }
#pragma unroll
            for (int p = 0; p < 2; p++) {
                uint32_t krow = kf * 16 + (lane & 15);
                uint32_t boff = krow * PB + (wn * 32 + p * 16 + ((lane >> 4) << 3)) * 2;
                uint32_t t[4];
                ldsm4t(t, base + B_HI + boff);
                bh[2 * p][0] = t[0]; bh[2 * p][1] = t[1];
                bh[2 * p + 1][0] = t[2]; bh[2 * p + 1][1] = t[3];
                ldsm4t(t, base + B_LO + boff);
                bl[2 * p][0] = t[0]; bl[2 * p][1] = t[1];
                bl[2 * p + 1][0] = t[2]; bl[2 * p + 1][1] = t[3];
            }
#pragma unroll
            for (int mf = 0; mf < 4; mf++)
#pragma unroll
                for (int nf = 0; nf < 4; nf++) {
                    mma16816(acc[mf][nf], ah[mf], bh[nf]);
                    mma16816(acc[mf][nf], ah[mf], bl[nf]);
                    mma16816(acc[mf][nf], al[mf], bh[nf]);
                }
        }
        if (more) store_chunk((kc + 1) & 1);
        __syncthreads();
    }

    // ---- epilogue ----
    int rb = wm * 64 + (lane >> 2);
    int cb = wn * 32 + (lane & 3) * 2;
    const float* be = bias + (size_t)e * NWID + n0;
#pragma unroll
    for (int mf = 0; mf < 4; mf++) {
#pragma unroll
        for (int h = 0; h < 2; h++) {
            int mloc = rb + mf * 16 + h * 8;
            int m = m0 + mloc;
            float scale = G1 ? 1.0f : g_wt[m];
            float* orow = Out + (size_t)m * NWID + n0;
#pragma unroll
            for (int nf = 0; nf < 4; nf++) {
                int c = cb + nf * 8;
                float2 bb = *(const float2*)(be + c);
                float v0 = acc[mf][nf][2 * h + 0] + bb.x;
                float v1 = acc[mf][nf][2 * h + 1] + bb.y;
                float2 o;
                if (G1) { o.x = gelu_erf(v0); o.y = gelu_erf(v1); }
                else    { o.x = scale * v0;   o.y = scale * v1; }
                *(float2*)(orow + c) = o;
            }
        }
    }
}

// ---------------- combine ----------------
__global__ __launch_bounds__(256) void combine_kernel(float* __restrict__ out) {
    int idx = blockIdx.x * blockDim.x + threadIdx.x;
    if (idx >= NTOK * (D_MODEL / 4)) return;
    int n  = idx / (D_MODEL / 4);
    int d4 = idx % (D_MODEL / 4);
    int s0 = g_slot_of[n * 2 + 0];
    int s1 = g_slot_of[n * 2 + 1];
    float4 a = *(const float4*)(g_y + (size_t)s0 * D_MODEL + d4 * 4);
    float4 b = *(const float4*)(g_y + (size_t)s1 * D_MODEL + d4 * 4);
    *(float4*)(out + (size_t)idx * 4) = make_float4(a.x + b.x, a.y + b.y, a.z + b.z, a.w + b.w);
}

// ---------------- launch ----------------
extern "C" void kernel_launch(void* const* d_in, const int* in_sizes, int n_in,
                              void* d_out, int out_size) {
    const float* x      = (const float*)d_in[0];
    const float* gate_w = (const float*)d_in[1];
    const float* w1     = (const float*)d_in[2];
    const float* b1     = (const float*)d_in[3];
    const float* w2     = (const float*)d_in[4];
    const float* b2     = (const float*)d_in[5];
    float* out = (float*)d_out;

    static int s_attr_done = 0;
    if (!s_attr_done) {
        cudaFuncSetAttribute(moe_gemm<true,  D_MODEL, D_HID>,
                             cudaFuncAttributeMaxDynamicSharedMemorySize, SMEM_DYN);
        cudaFuncSetAttribute(moe_gemm<false, D_HID, D_MODEL>,
                             cudaFuncAttributeMaxDynamicSharedMemorySize, SMEM_DYN);
        s_attr_done = 1;
    }

    init_kernel<<<1, 32>>>();
    router_kernel<<<NTOK / 8, 256>>>(x, gate_w);
    setup_kernel<<<1, 256>>>();
    scatter_kernel<<<NASSIGN / 256, 256>>>();
    moe_gemm<true,  D_MODEL, D_HID><<<dim3(D_HID / BN, MAXTILES), 256, SMEM_DYN>>>(x, w1, b1);
    moe_gemm<false, D_HID, D_MODEL><<<dim3(D_MODEL / BN, MAXTILES), 256, SMEM_DYN>>>(x, w2, b2);
    combine_kernel<<<(NTOK * (D_MODEL / 4) + 255) / 256, 256>>>(out);
}

// round 4
// speedup vs baseline: 2.6207x; 1.0366x over previous
#include <cuda_runtime.h>
#include <cuda_fp16.h>
#include <math.h>
#include <stdint.h>

// ---------------- problem constants ----------------
#define D_MODEL 768
#define D_HID   3072
#define NE      8
#define NTOK    2048
#define NASSIGN (NTOK*2)             // 4096
#define BM 128
#define BN 128
#define BK 32
#define MAXM     (NASSIGN + NE*BM)   // 5120
#define MAXTILES (NASSIGN/BM + NE)   // 40

// ---------------- smem layout (bytes, per buffer) ----------------
#define PA 80                        // A row pitch (32 fp16 = 64B data, odd 16B-chunk count)
#define PB 272                       // B row pitch (128 fp16 = 256B data, odd 16B-chunk count)
#define A_HI 0
#define A_LO (128*PA)                // 10240
#define B_OFF (2*128*PA)             // 20480
#define BUFSZ (2*128*PA + 32*PB)     // 29184
#define SMEM_DYN (2*BUFSZ)           // 58368

// ---------------- scratch ----------------
__device__ int   g_counts[NE];
__device__ int   g_cursor[NE];
__device__ int   g_tile_e[MAXTILES];
__device__ int   g_tile_m0[MAXTILES];
__device__ int   g_ntiles;
__device__ int   g_expert_of[NASSIGN];
__device__ float g_w_of[NASSIGN];
__device__ int   g_slot_of[NASSIGN];
__device__ int   g_tok[MAXM];
__device__ float g_wt[MAXM];
__device__ float g_h[(size_t)MAXM * D_HID];
__device__ float g_y[(size_t)MAXM * D_MODEL];

// ---------------- helpers ----------------
__device__ __forceinline__ uint32_t smem_u32(const void* p) {
    uint32_t a;
    asm("{ .reg .u64 t; cvta.to.shared.u64 t, %1; cvt.u32.u64 %0, t; }" : "=r"(a) : "l"(p));
    return a;
}
__device__ __forceinline__ void sts64(uint32_t addr, uint32_t x, uint32_t y) {
    asm volatile("st.shared.v2.b32 [%0], {%1, %2};" :: "r"(addr), "r"(x), "r"(y) : "memory");
}
__device__ __forceinline__ void ldsm4(uint32_t* r, uint32_t addr) {
    asm volatile("ldmatrix.sync.aligned.m8n8.x4.shared.b16 {%0,%1,%2,%3}, [%4];"
                 : "=r"(r[0]), "=r"(r[1]), "=r"(r[2]), "=r"(r[3]) : "r"(addr));
}
__device__ __forceinline__ void ldsm4t(uint32_t* r, uint32_t addr) {
    asm volatile("ldmatrix.sync.aligned.m8n8.x4.trans.shared.b16 {%0,%1,%2,%3}, [%4];"
                 : "=r"(r[0]), "=r"(r[1]), "=r"(r[2]), "=r"(r[3]) : "r"(addr));
}
__device__ __forceinline__ void mma16816(float* d, const uint32_t* a, const uint32_t* b) {
    asm volatile("mma.sync.aligned.m16n8k16.row.col.f32.f16.f16.f32 "
                 "{%0,%1,%2,%3}, {%4,%5,%6,%7}, {%8,%9}, {%0,%1,%2,%3};"
                 : "+f"(d[0]), "+f"(d[1]), "+f"(d[2]), "+f"(d[3])
                 : "r"(a[0]), "r"(a[1]), "r"(a[2]), "r"(a[3]), "r"(b[0]), "r"(b[1]));
}
__device__ __forceinline__ float gelu_erf(float v) {
    return 0.5f * v * (1.0f + erff(v * 0.7071067811865476f));
}
__device__ __forceinline__ uint32_t pk_hi(float a, float b, float& ra, float& rb) {
    __half2 h = __floats2half2_rn(a, b);
    float2 f = __half22float2(h);
    ra = a - f.x; rb = b - f.y;
    uint32_t u; memcpy(&u, &h, 4); return u;
}
__device__ __forceinline__ uint32_t pk(float a, float b) {
    __half2 h = __floats2half2_rn(a, b);
    uint32_t u; memcpy(&u, &h, 4); return u;
}

// ---------------- router path ----------------
__global__ void init_kernel() {
    if (threadIdx.x < NE) g_counts[threadIdx.x] = 0;
}

__global__ __launch_bounds__(256) void router_kernel(const float* __restrict__ x,
                                                     const float* __restrict__ gate_w) {
    int warp = (blockIdx.x * blockDim.x + threadIdx.x) >> 5;
    int lane = threadIdx.x & 31;
    if (warp >= NTOK) return;
    const float* xr = x + (size_t)warp * D_MODEL;
    float acc[NE];
#pragma unroll
    for (int e = 0; e < NE; e++) acc[e] = 0.f;
    for (int d = lane; d < D_MODEL; d += 32) {
        float xv = xr[d];
        const float4* gw = (const float4*)(gate_w + (size_t)d * NE);
        float4 a = gw[0], b = gw[1];
        acc[0] = fmaf(xv, a.x, acc[0]); acc[1] = fmaf(xv, a.y, acc[1]);
        acc[2] = fmaf(xv, a.z, acc[2]); acc[3] = fmaf(xv, a.w, acc[3]);
        acc[4] = fmaf(xv, b.x, acc[4]); acc[5] = fmaf(xv, b.y, acc[5]);
        acc[6] = fmaf(xv, b.z, acc[6]); acc[7] = fmaf(xv, b.w, acc[7]);
    }
#pragma unroll
    for (int e = 0; e < NE; e++)
#pragma unroll
        for (int o = 16; o > 0; o >>= 1)
            acc[e] += __shfl_xor_sync(0xffffffffu, acc[e], o);
    if (lane == 0) {
        float mx = acc[0];
#pragma unroll
        for (int e = 1; e < NE; e++) mx = fmaxf(mx, acc[e]);
        float p[NE]; float s = 0.f;
#pragma unroll
        for (int e = 0; e < NE; e++) { p[e] = expf(acc[e] - mx); s += p[e]; }
        float inv = 1.0f / s;
#pragma unroll
        for (int e = 0; e < NE; e++) p[e] *= inv;
        int i0 = 0;
#pragma unroll
        for (int e = 1; e < NE; e++) if (p[e] > p[i0]) i0 = e;
        int i1 = (i0 == 0) ? 1 : 0;
#pragma unroll
        for (int e = 0; e < NE; e++) if (e != i0 && p[e] > p[i1]) i1 = e;
        float w0 = p[i0], w1 = p[i1];
        float isw = 1.0f / (w0 + w1);
        g_expert_of[warp * 2 + 0] = i0;
        g_expert_of[warp * 2 + 1] = i1;
        g_w_of[warp * 2 + 0] = w0 * isw;
        g_w_of[warp * 2 + 1] = w1 * isw;
        atomicAdd(&g_counts[i0], 1);
        atomicAdd(&g_counts[i1], 1);
    }
}

__global__ void setup_kernel() {
    if (threadIdx.x == 0) {
        int off = 0, t = 0;
        for (int e = 0; e < NE; e++) {
            g_cursor[e] = off;
            int nt = (g_counts[e] + BM - 1) / BM;
            for (int i = 0; i < nt; i++) { g_tile_e[t] = e; g_tile_m0[t] = off + i * BM; t++; }
            off += nt * BM;
        }
        g_ntiles = t;
    }
    __syncthreads();
    for (int i = threadIdx.x; i < MAXM; i += blockDim.x) { g_tok[i] = -1; g_wt[i] = 0.f; }
}

__global__ void scatter_kernel() {
    int idx = blockIdx.x * blockDim.x + threadIdx.x;
    if (idx >= NASSIGN) return;
    int e = g_expert_of[idx];
    int slot = atomicAdd(&g_cursor[e], 1);
    g_tok[slot] = idx >> 1;
    g_wt[slot] = g_w_of[idx];
    g_slot_of[idx] = slot;
}

// ---------------- grouped GEMM via mma.sync (fp16 2-term split: A=hi+lo, B=hi) ----------------
template<bool G1, int KTOT, int NWID>
__global__ __launch_bounds__(256) void moe_gemm(const float* __restrict__ Aext,
                                                const float* __restrict__ Wsrc,
                                                const float* __restrict__ bias) {
    int tile = blockIdx.y;
    if (tile >= g_ntiles) return;
    int e  = g_tile_e[tile];
    int m0 = g_tile_m0[tile];
    int n0 = blockIdx.x * BN;
    const float* W = Wsrc + (size_t)e * KTOT * NWID;
    float* Out = G1 ? g_h : g_y;

    extern __shared__ char smem[];
    uint32_t sb = smem_u32(smem);
    __shared__ int s_tok[BM];

    int tid = threadIdx.x, lane = tid & 31, wid = tid >> 5;
    int wm = wid >> 2, wn = wid & 3;

    if (G1 && tid < BM) s_tok[tid] = g_tok[m0 + tid];
    __syncthreads();

    const int aq = tid & 7, ar0 = tid >> 3;      // A: float4 col aq, rows ar0 + 32r
    const int bq = tid & 31, bk0 = tid >> 5;     // B: float4 col bq, k-rows bk0 + 8r

    int atok[4];
    const float* aRow[4];
    if (G1) {
#pragma unroll
        for (int r = 0; r < 4; r++) {
            atok[r] = s_tok[ar0 + 32 * r];
            aRow[r] = Aext + (size_t)((atok[r] < 0) ? 0 : atok[r]) * KTOT;
        }
    } else {
#pragma unroll
        for (int r = 0; r < 4; r++) {
            atok[r] = 0;
            aRow[r] = g_h + (size_t)(m0 + ar0 + 32 * r) * KTOT;
        }
    }

    float4 pa[4], pb[4];
    const int NCH = KTOT / BK;

    auto load_chunk = [&](int kc) {
#pragma unroll
        for (int r = 0; r < 4; r++) {
            if (G1 && atok[r] < 0) pa[r] = make_float4(0.f, 0.f, 0.f, 0.f);
            else                   pa[r] = *(const float4*)(aRow[r] + kc * BK + aq * 4);
        }
#pragma unroll
        for (int r = 0; r < 4; r++)
            pb[r] = *(const float4*)(W + (size_t)(kc * BK + bk0 + 8 * r) * NWID + n0 + bq * 4);
    };
    auto store_chunk = [&](int buf) {
        uint32_t base = sb + buf * BUFSZ;
#pragma unroll
        for (int r = 0; r < 4; r++) {
            float rx, ry, rz, rw;
            uint32_t h0 = pk_hi(pa[r].x, pa[r].y, rx, ry);
            uint32_t h1 = pk_hi(pa[r].z, pa[r].w, rz, rw);
            uint32_t l0 = pk(rx, ry), l1 = pk(rz, rw);
            uint32_t off = (uint32_t)(ar0 + 32 * r) * PA + aq * 8;
            sts64(base + A_HI + off, h0, h1);
            sts64(base + A_LO + off, l0, l1);
        }
#pragma unroll
        for (int r = 0; r < 4; r++) {
            uint32_t h0 = pk(pb[r].x, pb[r].y);
            uint32_t h1 = pk(pb[r].z, pb[r].w);
            uint32_t off = (uint32_t)(bk0 + 8 * r) * PB + bq * 8;
            sts64(base + B_OFF + off, h0, h1);
        }
    };

    float acc[4][4][4];
#pragma unroll
    for (int i = 0; i < 4; i++)
#pragma unroll
        for (int j = 0; j < 4; j++)
#pragma unroll
            for (int k = 0; k < 4; k++) acc[i][j][k] = 0.f;

    load_chunk(0);
    store_chunk(0);
    __syncthreads();

#pragma unroll 1
    for (int kc = 0; kc < NCH; kc++) {
        bool more = (kc + 1 < NCH);
        if (more) load_chunk(kc + 1);

        uint32_t base = sb + (kc & 1) * BUFSZ;
#pragma unroll
        for (int kf = 0; kf < 2; kf++) {
            uint32_t ah[4][4], al[4][4], bh[4][2];
#pragma unroll
            for (int mf = 0; mf < 4; mf++) {
                uint32_t arow = wm * 64 + mf * 16 + (lane & 15);
                uint32_t aoff = arow * PA + kf * 32 + ((lane >> 4) << 4);
                ldsm4(ah[mf], base + A_HI + aoff);
                ldsm4(al[mf], base + A_LO + aoff);
            }
#pragma unroll
            for (int p = 0; p < 2; p++) {
                uint32_t krow = kf * 16 + (lane & 15);
                uint32_t boff = krow * PB + (wn * 32 + p * 16 + ((lane >> 4) << 3)) * 2;
                uint32_t t[4];
                ldsm4t(t, base + B_OFF + boff);
                bh[2 * p][0] = t[0]; bh[2 * p][1] = t[1];
                bh[2 * p + 1][0] = t[2]; bh[2 * p + 1][1] = t[3];
            }
#pragma unroll
            for (int mf = 0; mf < 4; mf++)
#pragma unroll
                for (int nf = 0; nf < 4; nf++) {
                    mma16816(acc[mf][nf], ah[mf], bh[nf]);
                    mma16816(acc[mf][nf], al[mf], bh[nf]);
                }
        }
        if (more) store_chunk((kc + 1) & 1);
        __syncthreads();
    }

    // ---- epilogue ----
    int rb = wm * 64 + (lane >> 2);
    int cb = wn * 32 + (lane & 3) * 2;
    const float* be = bias + (size_t)e * NWID + n0;
#pragma unroll
    for (int mf = 0; mf < 4; mf++) {
#pragma unroll
        for (int h = 0; h < 2; h++) {
            int mloc = rb + mf * 16 + h * 8;
            int m = m0 + mloc;
            float scale = G1 ? 1.0f : g_wt[m];
            float* orow = Out + (size_t)m * NWID + n0;
#pragma unroll
            for (int nf = 0; nf < 4; nf++) {
                int c = cb + nf * 8;
                float2 bb = *(const float2*)(be + c);
                float v0 = acc[mf][nf][2 * h + 0] + bb.x;
                float v1 = acc[mf][nf][2 * h + 1] + bb.y;
                float2 o;
                if (G1) { o.x = gelu_erf(v0); o.y = gelu_erf(v1); }
                else    { o.x = scale * v0;   o.y = scale * v1; }
                *(float2*)(orow + c) = o;
            }
        }
    }
}

// ---------------- combine ----------------
__global__ __launch_bounds__(256) void combine_kernel(float* __restrict__ out) {
    int idx = blockIdx.x * blockDim.x + threadIdx.x;
    if (idx >= NTOK * (D_MODEL / 4)) return;
    int n  = idx / (D_MODEL / 4);
    int d4 = idx % (D_MODEL / 4);
    int s0 = g_slot_of[n * 2 + 0];
    int s1 = g_slot_of[n * 2 + 1];
    float4 a = *(const float4*)(g_y + (size_t)s0 * D_MODEL + d4 * 4);
    float4 b = *(const float4*)(g_y + (size_t)s1 * D_MODEL + d4 * 4);
    *(float4*)(out + (size_t)idx * 4) = make_float4(a.x + b.x, a.y + b.y, a.z + b.z, a.w + b.w);
}

// ---------------- launch ----------------
extern "C" void kernel_launch(void* const* d_in, const int* in_sizes, int n_in,
                              void* d_out, int out_size) {
    const float* x      = (const float*)d_in[0];
    const float* gate_w = (const float*)d_in[1];
    const float* w1     = (const float*)d_in[2];
    const float* b1     = (const float*)d_in[3];
    const float* w2     = (const float*)d_in[4];
    const float* b2     = (const float*)d_in[5];
    float* out = (float*)d_out;

    static int s_attr_done = 0;
    if (!s_attr_done) {
        cudaFuncSetAttribute(moe_gemm<true,  D_MODEL, D_HID>,
                             cudaFuncAttributeMaxDynamicSharedMemorySize, SMEM_DYN);
        cudaFuncSetAttribute(moe_gemm<false, D_HID, D_MODEL>,
                             cudaFuncAttributeMaxDynamicSharedMemorySize, SMEM_DYN);
        s_attr_done = 1;
    }

    init_kernel<<<1, 32>>>();
    router_kernel<<<NTOK / 8, 256>>>(x, gate_w);
    setup_kernel<<<1, 256>>>();
    scatter_kernel<<<NASSIGN / 256, 256>>>();
    moe_gemm<true,  D_MODEL, D_HID><<<dim3(D_HID / BN, MAXTILES), 256, SMEM_DYN>>>(x, w1, b1);
    moe_gemm<false, D_HID, D_MODEL><<<dim3(D_MODEL / BN, MAXTILES), 256, SMEM_DYN>>>(x, w2, b2);
    combine_kernel<<<(NTOK * (D_MODEL / 4) + 255) / 256, 256>>>(out);
}

// round 9
// speedup vs baseline: 2.9549x; 1.1275x over previous
#include <cuda_runtime.h>
#include <cuda_fp16.h>
#include <math.h>
#include <stdint.h>

// ---------------- problem constants ----------------
#define D_MODEL 768
#define D_HID   3072
#define NE      8
#define NTOK    2048
#define NASSIGN (NTOK*2)             // 4096
#define BM 128
#define BN 128
#define BK 32
#define MAXM     (NASSIGN + NE*BM)   // 5120
#define MAXTILES (NASSIGN/BM + NE)   // 40

// ---------------- smem layout (bytes, per buffer) ----------------
#define PA 80                        // A row pitch (32 fp16 = 64B data + 16B pad)
#define PB 272                       // B row pitch (128 fp16 = 256B data + 16B pad)
#define ST_ALO 10240                 // 128*PA
#define ST_B   20480
#define STAGE_SZ 29184               // 2*128*PA + 32*PB
#define SMEM_DYN (2*STAGE_SZ)        // 58368

// ---------------- scratch ----------------
__device__ int    g_counts[NE];
__device__ int    g_cursor[NE];
__device__ int    g_tile_e[MAXTILES];
__device__ int    g_tile_m0[MAXTILES];
__device__ int    g_ntiles;
__device__ int    g_expert_of[NASSIGN];
__device__ float  g_w_of[NASSIGN];
__device__ int    g_tok[MAXM];
__device__ float  g_wt[MAXM];
__device__ __align__(256) __half g_xh[(size_t)NTOK * D_MODEL];
__device__ __align__(256) __half g_xl[(size_t)NTOK * D_MODEL];
__device__ __align__(256) __half g_w1h[(size_t)NE * D_MODEL * D_HID];
__device__ __align__(256) __half g_w2h[(size_t)NE * D_HID * D_MODEL];
__device__ __align__(256) __half g_hh[(size_t)MAXM * D_HID];
__device__ __align__(256) __half g_hl[(size_t)MAXM * D_HID];

// ---------------- helpers ----------------
__device__ __forceinline__ uint32_t smem_u32(const void* p) {
    uint32_t a;
    asm("{ .reg .u64 t; cvta.to.shared.u64 t, %1; cvt.u32.u64 %0, t; }" : "=r"(a) : "l"(p));
    return a;
}
__device__ __forceinline__ void sts128(uint32_t addr, uint4 v) {
    asm volatile("st.shared.v4.b32 [%0], {%1, %2, %3, %4};"
                 :: "r"(addr), "r"(v.x), "r"(v.y), "r"(v.z), "r"(v.w) : "memory");
}
__device__ __forceinline__ void ldsm4(uint32_t* r, uint32_t addr) {
    asm volatile("ldmatrix.sync.aligned.m8n8.x4.shared.b16 {%0,%1,%2,%3}, [%4];"
                 : "=r"(r[0]), "=r"(r[1]), "=r"(r[2]), "=r"(r[3]) : "r"(addr));
}
__device__ __forceinline__ void ldsm4t(uint32_t* r, uint32_t addr) {
    asm volatile("ldmatrix.sync.aligned.m8n8.x4.trans.shared.b16 {%0,%1,%2,%3}, [%4];"
                 : "=r"(r[0]), "=r"(r[1]), "=r"(r[2]), "=r"(r[3]) : "r"(addr));
}
__device__ __forceinline__ void mma16816(float* d, const uint32_t* a, const uint32_t* b) {
    asm volatile("mma.sync.aligned.m16n8k16.row.col.f32.f16.f16.f32 "
                 "{%0,%1,%2,%3}, {%4,%5,%6,%7}, {%8,%9}, {%0,%1,%2,%3};"
                 : "+f"(d[0]), "+f"(d[1]), "+f"(d[2]), "+f"(d[3])
                 : "r"(a[0]), "r"(a[1]), "r"(a[2]), "r"(a[3]), "r"(b[0]), "r"(b[1]));
}
__device__ __forceinline__ float gelu_erf(float v) {
    return 0.5f * v * (1.0f + erff(v * 0.7071067811865476f));
}

// ---------------- prepass kernels ----------------
// NOTE: destination must be referenced from DEVICE code — passing a __device__
// symbol as a host-side kernel argument passes the host shadow address (bug in R5-R8).
template<bool W1>
__global__ __launch_bounds__(256) void convert_w_kernel(const float* __restrict__ src, int n4) {
    __half* dst = W1 ? g_w1h : g_w2h;
    int i = blockIdx.x * blockDim.x + threadIdx.x;
    if (i >= n4) return;
    float4 v = ((const float4*)src)[i];
    ((__half2*)dst)[2 * i]     = __floats2half2_rn(v.x, v.y);
    ((__half2*)dst)[2 * i + 1] = __floats2half2_rn(v.z, v.w);
}

// split x into hi/lo fp16; also zero d_out (same index space: NTOK*D_MODEL/4)
__global__ __launch_bounds__(256) void convert_x_kernel(const float* __restrict__ x,
                                                        float* __restrict__ out) {
    int i = blockIdx.x * blockDim.x + threadIdx.x;
    if (i >= NTOK * D_MODEL / 4) return;
    float4 v = ((const float4*)x)[i];
    __half2 h0 = __floats2half2_rn(v.x, v.y);
    __half2 h1 = __floats2half2_rn(v.z, v.w);
    float2 f0 = __half22float2(h0), f1 = __half22float2(h1);
    __half2 l0 = __floats2half2_rn(v.x - f0.x, v.y - f0.y);
    __half2 l1 = __floats2half2_rn(v.z - f1.x, v.w - f1.y);
    ((__half2*)g_xh)[2 * i] = h0; ((__half2*)g_xh)[2 * i + 1] = h1;
    ((__half2*)g_xl)[2 * i] = l0; ((__half2*)g_xl)[2 * i + 1] = l1;
    ((float4*)out)[i] = make_float4(0.f, 0.f, 0.f, 0.f);
}

// ---------------- router path ----------------
__global__ void init_kernel() {
    if (threadIdx.x < NE) g_counts[threadIdx.x] = 0;
}

__global__ __launch_bounds__(256) void router_kernel(const float* __restrict__ x,
                                                     const float* __restrict__ gate_w) {
    int warp = (blockIdx.x * blockDim.x + threadIdx.x) >> 5;
    int lane = threadIdx.x & 31;
    if (warp >= NTOK) return;
    const float* xr = x + (size_t)warp * D_MODEL;
    float acc[NE];
#pragma unroll
    for (int e = 0; e < NE; e++) acc[e] = 0.f;
    for (int d = lane; d < D_MODEL; d += 32) {
        float xv = xr[d];
        const float4* gw = (const float4*)(gate_w + (size_t)d * NE);
        float4 a = gw[0], b = gw[1];
        acc[0] = fmaf(xv, a.x, acc[0]); acc[1] = fmaf(xv, a.y, acc[1]);
        acc[2] = fmaf(xv, a.z, acc[2]); acc[3] = fmaf(xv, a.w, acc[3]);
        acc[4] = fmaf(xv, b.x, acc[4]); acc[5] = fmaf(xv, b.y, acc[5]);
        acc[6] = fmaf(xv, b.z, acc[6]); acc[7] = fmaf(xv, b.w, acc[7]);
    }
#pragma unroll
    for (int e = 0; e < NE; e++)
#pragma unroll
        for (int o = 16; o > 0; o >>= 1)
            acc[e] += __shfl_xor_sync(0xffffffffu, acc[e], o);
    if (lane == 0) {
        float mx = acc[0];
#pragma unroll
        for (int e = 1; e < NE; e++) mx = fmaxf(mx, acc[e]);
        float p[NE]; float s = 0.f;
#pragma unroll
        for (int e = 0; e < NE; e++) { p[e] = expf(acc[e] - mx); s += p[e]; }
        float inv = 1.0f / s;
#pragma unroll
        for (int e = 0; e < NE; e++) p[e] *= inv;
        int i0 = 0;
#pragma unroll
        for (int e = 1; e < NE; e++) if (p[e] > p[i0]) i0 = e;
        int i1 = (i0 == 0) ? 1 : 0;
#pragma unroll
        for (int e = 0; e < NE; e++) if (e != i0 && p[e] > p[i1]) i1 = e;
        float w0 = p[i0], w1 = p[i1];
        float isw = 1.0f / (w0 + w1);
        g_expert_of[warp * 2 + 0] = i0;
        g_expert_of[warp * 2 + 1] = i1;
        g_w_of[warp * 2 + 0] = w0 * isw;
        g_w_of[warp * 2 + 1] = w1 * isw;
        atomicAdd(&g_counts[i0], 1);
        atomicAdd(&g_counts[i1], 1);
    }
}

__global__ void setup_kernel() {
    if (threadIdx.x == 0) {
        int off = 0, t = 0;
        for (int e = 0; e < NE; e++) {
            g_cursor[e] = off;
            int nt = (g_counts[e] + BM - 1) / BM;
            for (int i = 0; i < nt; i++) { g_tile_e[t] = e; g_tile_m0[t] = off + i * BM; t++; }
            off += nt * BM;
        }
        g_ntiles = t;
    }
    __syncthreads();
    for (int i = threadIdx.x; i < MAXM; i += blockDim.x) { g_tok[i] = -1; g_wt[i] = 0.f; }
}

__global__ void scatter_kernel() {
    int idx = blockIdx.x * blockDim.x + threadIdx.x;
    if (idx >= NASSIGN) return;
    int e = g_expert_of[idx];
    int slot = atomicAdd(&g_cursor[e], 1);
    g_tok[slot] = idx >> 1;
    g_wt[slot] = g_w_of[idx];
}

// ---------------- grouped GEMM: register-staged double buffer, fp16 sources ----------------
template<bool G1, int KTOT, int NWID>
__global__ __launch_bounds__(256) void moe_gemm(const float* __restrict__ bias,
                                                float* __restrict__ out) {
    int tile = blockIdx.y;
    if (tile >= g_ntiles) return;
    int e  = g_tile_e[tile];
    int m0 = g_tile_m0[tile];
    int n0 = blockIdx.x * BN;
    const __half* Wh = (G1 ? g_w1h : g_w2h) + (size_t)e * KTOT * NWID;

    extern __shared__ char smem[];
    uint32_t sb = smem_u32(smem);
    __shared__ int   s_tok[BM];
    __shared__ float s_wt[BM];

    int tid = threadIdx.x, lane = tid & 31, wid = tid >> 5;
    int wm = wid >> 2, wn = wid & 3;

    if (tid < BM) { s_tok[tid] = g_tok[m0 + tid]; s_wt[tid] = g_wt[m0 + tid]; }
    __syncthreads();

    // copy mapping: A rows ar, ar+64 (4 uint4/row, col aq); B k-rows bk, bk+16 (16 uint4/row, col bq)
    const int aq = tid & 3, ar = tid >> 2;
    const int bq = tid & 15, bk = tid >> 4;

    const char *aHp[2], *aLp[2];
    bool av[2];
#pragma unroll
    for (int r = 0; r < 2; r++) {
        int row = ar + 64 * r;
        if (G1) {
            int tok = s_tok[row];
            av[r] = (tok >= 0);
            size_t ro = (size_t)(tok < 0 ? 0 : tok) * KTOT * 2;
            aHp[r] = (const char*)g_xh + ro;
            aLp[r] = (const char*)g_xl + ro;
        } else {
            av[r] = true;
            size_t ro = (size_t)(m0 + row) * KTOT * 2;
            aHp[r] = (const char*)g_hh + ro;
            aLp[r] = (const char*)g_hl + ro;
        }
    }
    const char* bp[2];
#pragma unroll
    for (int r = 0; r < 2; r++)
        bp[r] = (const char*)(Wh + (size_t)(bk + 16 * r) * NWID + n0);

    uint4 pah[2], pal[2], pb[2];
    const uint4 z4 = make_uint4(0, 0, 0, 0);
    const int NCH = KTOT / BK;

    auto load_chunk = [&](int kc) {
        size_t ko = (size_t)kc * 64 + aq * 16;
#pragma unroll
        for (int r = 0; r < 2; r++) {
            pah[r] = av[r] ? *(const uint4*)(aHp[r] + ko) : z4;
            pal[r] = av[r] ? *(const uint4*)(aLp[r] + ko) : z4;
        }
        size_t kb = (size_t)kc * BK * NWID * 2 + bq * 16;
#pragma unroll
        for (int r = 0; r < 2; r++)
            pb[r] = *(const uint4*)(bp[r] + kb);
    };
    auto store_chunk = [&](int buf) {
        uint32_t base = sb + buf * STAGE_SZ;
#pragma unroll
        for (int r = 0; r < 2; r++) {
            uint32_t off = (uint32_t)(ar + 64 * r) * PA + aq * 16;
            sts128(base + off, pah[r]);
            sts128(base + ST_ALO + off, pal[r]);
        }
#pragma unroll
        for (int r = 0; r < 2; r++) {
            uint32_t off = (uint32_t)(bk + 16 * r) * PB + bq * 16;
            sts128(base + ST_B + off, pb[r]);
        }
    };

    float acc[4][4][4];
#pragma unroll
    for (int i = 0; i < 4; i++)
#pragma unroll
        for (int j = 0; j < 4; j++)
#pragma unroll
            for (int k = 0; k < 4; k++) acc[i][j][k] = 0.f;

    load_chunk(0);
    store_chunk(0);
    __syncthreads();

#pragma unroll 1
    for (int kc = 0; kc < NCH; kc++) {
        bool more = (kc + 1 < NCH);
        if (more) load_chunk(kc + 1);

        uint32_t base = sb + (kc & 1) * STAGE_SZ;
#pragma unroll
        for (int kf = 0; kf < 2; kf++) {
            uint32_t ah[4][4], al[4][4], bh[4][2];
#pragma unroll
            for (int mf = 0; mf < 4; mf++) {
                uint32_t arr = wm * 64 + mf * 16 + (lane & 15);
                uint32_t aoff = arr * PA + kf * 32 + ((lane >> 4) << 4);
                ldsm4(ah[mf], base + aoff);
                ldsm4(al[mf], base + ST_ALO + aoff);
            }
#pragma unroll
            for (int p = 0; p < 2; p++) {
                uint32_t kr = kf * 16 + (lane & 15);
                uint32_t boff = kr * PB + (wn * 32 + p * 16 + ((lane >> 4) << 3)) * 2;
                uint32_t t[4];
                ldsm4t(t, base + ST_B + boff);
                bh[2 * p][0] = t[0]; bh[2 * p][1] = t[1];
                bh[2 * p + 1][0] = t[2]; bh[2 * p + 1][1] = t[3];
            }
#pragma unroll
            for (int mf = 0; mf < 4; mf++)
#pragma unroll
                for (int nf = 0; nf < 4; nf++) {
                    mma16816(acc[mf][nf], ah[mf], bh[nf]);
                    mma16816(acc[mf][nf], al[mf], bh[nf]);
                }
        }
        if (more) store_chunk((kc + 1) & 1);
        __syncthreads();
    }

    // ---- epilogue ----
    int rb = wm * 64 + (lane >> 2);
    int cb = wn * 32 + (lane & 3) * 2;
    const float* be = bias + (size_t)e * NWID + n0;
#pragma unroll
    for (int mf = 0; mf < 4; mf++) {
#pragma unroll
        for (int h = 0; h < 2; h++) {
            int mloc = rb + mf * 16 + h * 8;
            int m = m0 + mloc;
            if (G1) {
                __half2* hrow = (__half2*)(g_hh + (size_t)m * NWID + n0);
                __half2* lrow = (__half2*)(g_hl + (size_t)m * NWID + n0);
#pragma unroll
                for (int nf = 0; nf < 4; nf++) {
                    int c = cb + nf * 8;
                    float2 bb = *(const float2*)(be + c);
                    float v0 = gelu_erf(acc[mf][nf][2 * h + 0] + bb.x);
                    float v1 = gelu_erf(acc[mf][nf][2 * h + 1] + bb.y);
                    __half2 hh = __floats2half2_rn(v0, v1);
                    float2 f = __half22float2(hh);
                    __half2 hl = __floats2half2_rn(v0 - f.x, v1 - f.y);
                    hrow[c >> 1] = hh;
                    lrow[c >> 1] = hl;
                }
            } else {
                float wt = s_wt[mloc];
                if (wt != 0.f) {
                    int tok = s_tok[mloc];
                    float* orow = out + (size_t)tok * NWID + n0;
#pragma unroll
                    for (int nf = 0; nf < 4; nf++) {
                        int c = cb + nf * 8;
                        float2 bb = *(const float2*)(be + c);
                        atomicAdd(orow + c,     wt * (acc[mf][nf][2 * h + 0] + bb.x));
                        atomicAdd(orow + c + 1, wt * (acc[mf][nf][2 * h + 1] + bb.y));
                    }
                }
            }
        }
    }
}

// ---------------- launch ----------------
extern "C" void kernel_launch(void* const* d_in, const int* in_sizes, int n_in,
                              void* d_out, int out_size) {
    const float* x      = (const float*)d_in[0];
    const float* gate_w = (const float*)d_in[1];
    const float* w1     = (const float*)d_in[2];
    const float* b1     = (const float*)d_in[3];
    const float* w2     = (const float*)d_in[4];
    const float* b2     = (const float*)d_in[5];
    float* out = (float*)d_out;

    cudaFuncSetAttribute(moe_gemm<true,  D_MODEL, D_HID>,
                         cudaFuncAttributeMaxDynamicSharedMemorySize, SMEM_DYN);
    cudaFuncSetAttribute(moe_gemm<false, D_HID, D_MODEL>,
                         cudaFuncAttributeMaxDynamicSharedMemorySize, SMEM_DYN);

    const int WN4 = NE * D_MODEL * D_HID / 4;   // 4718592
    init_kernel<<<1, 32>>>();
    router_kernel<<<NTOK / 8, 256>>>(x, gate_w);
    setup_kernel<<<1, 256>>>();
    scatter_kernel<<<NASSIGN / 256, 256>>>();
    convert_x_kernel<<<(NTOK * D_MODEL / 4 + 255) / 256, 256>>>(x, out);
    convert_w_kernel<true ><<<(WN4 + 255) / 256, 256>>>(w1, WN4);
    convert_w_kernel<false><<<(WN4 + 255) / 256, 256>>>(w2, WN4);
    moe_gemm<true,  D_MODEL, D_HID><<<dim3(D_HID / BN, MAXTILES), 256, SMEM_DYN>>>(b1, out);
    moe_gemm<false, D_HID, D_MODEL><<<dim3(D_MODEL / BN, MAXTILES), 256, SMEM_DYN>>>(b2, out);
}

// round 10
// speedup vs baseline: 4.7486x; 1.6070x over previous
#include <cuda_runtime.h>
#include <cuda_fp16.h>
#include <math.h>
#include <stdint.h>

// ---------------- problem constants ----------------
#define D_MODEL 768
#define D_HID   3072
#define NE      8
#define NTOK    2048
#define NASSIGN (NTOK*2)             // 4096
#define BM 128
#define BN 128
#define BK 32
#define MAXM     (NASSIGN + NE*BM)   // 5120
#define MAXTILES (NASSIGN/BM + NE)   // 40

// ---------------- smem layout (bytes, per buffer) ----------------
#define PA 80                        // A row pitch (32 fp16 = 64B data + 16B pad)
#define PB 272                       // B row pitch (128 fp16 = 256B data + 16B pad)
#define ST_B   10240                 // 128*PA
#define STAGE_SZ 18944               // 128*PA + 32*PB
#define SMEM_DYN (2*STAGE_SZ)        // 37888

// ---------------- scratch ----------------
__device__ int    g_counts[NE];
__device__ int    g_cursor[NE];
__device__ int    g_tile_e[MAXTILES];
__device__ int    g_tile_m0[MAXTILES];
__device__ int    g_ntiles;
__device__ int    g_expert_of[NASSIGN];
__device__ float  g_w_of[NASSIGN];
__device__ int    g_tok[MAXM];
__device__ float  g_wt[MAXM];
__device__ __align__(256) __half g_xh[(size_t)NTOK * D_MODEL];
__device__ __align__(256) __half g_w1h[(size_t)NE * D_MODEL * D_HID];
__device__ __align__(256) __half g_w2h[(size_t)NE * D_HID * D_MODEL];
__device__ __align__(256) __half g_hh[(size_t)MAXM * D_HID];

// ---------------- helpers ----------------
__device__ __forceinline__ uint32_t smem_u32(const void* p) {
    uint32_t a;
    asm("{ .reg .u64 t; cvta.to.shared.u64 t, %1; cvt.u32.u64 %0, t; }" : "=r"(a) : "l"(p));
    return a;
}
__device__ __forceinline__ void sts128(uint32_t addr, uint4 v) {
    asm volatile("st.shared.v4.b32 [%0], {%1, %2, %3, %4};"
                 :: "r"(addr), "r"(v.x), "r"(v.y), "r"(v.z), "r"(v.w) : "memory");
}
__device__ __forceinline__ void ldsm4(uint32_t* r, uint32_t addr) {
    asm volatile("ldmatrix.sync.aligned.m8n8.x4.shared.b16 {%0,%1,%2,%3}, [%4];"
                 : "=r"(r[0]), "=r"(r[1]), "=r"(r[2]), "=r"(r[3]) : "r"(addr));
}
__device__ __forceinline__ void ldsm4t(uint32_t* r, uint32_t addr) {
    asm volatile("ldmatrix.sync.aligned.m8n8.x4.trans.shared.b16 {%0,%1,%2,%3}, [%4];"
                 : "=r"(r[0]), "=r"(r[1]), "=r"(r[2]), "=r"(r[3]) : "r"(addr));
}
__device__ __forceinline__ void mma16816(float* d, const uint32_t* a, const uint32_t* b) {
    asm volatile("mma.sync.aligned.m16n8k16.row.col.f32.f16.f16.f32 "
                 "{%0,%1,%2,%3}, {%4,%5,%6,%7}, {%8,%9}, {%0,%1,%2,%3};"
                 : "+f"(d[0]), "+f"(d[1]), "+f"(d[2]), "+f"(d[3])
                 : "r"(a[0]), "r"(a[1]), "r"(a[2]), "r"(a[3]), "r"(b[0]), "r"(b[1]));
}
__device__ __forceinline__ float gelu_erf(float v) {
    return 0.5f * v * (1.0f + erff(v * 0.7071067811865476f));
}

// ---------------- prepass kernels (dst referenced from device code!) ----------------
template<bool W1>
__global__ __launch_bounds__(256) void convert_w_kernel(const float* __restrict__ src, int n4) {
    __half* dst = W1 ? g_w1h : g_w2h;
    int i = blockIdx.x * blockDim.x + threadIdx.x;
    if (i >= n4) return;
    float4 v = ((const float4*)src)[i];
    ((__half2*)dst)[2 * i]     = __floats2half2_rn(v.x, v.y);
    ((__half2*)dst)[2 * i + 1] = __floats2half2_rn(v.z, v.w);
}

// x -> fp16; also zero d_out (same index space: NTOK*D_MODEL/4)
__global__ __launch_bounds__(256) void convert_x_kernel(const float* __restrict__ x,
                                                        float* __restrict__ out) {
    int i = blockIdx.x * blockDim.x + threadIdx.x;
    if (i >= NTOK * D_MODEL / 4) return;
    float4 v = ((const float4*)x)[i];
    ((__half2*)g_xh)[2 * i]     = __floats2half2_rn(v.x, v.y);
    ((__half2*)g_xh)[2 * i + 1] = __floats2half2_rn(v.z, v.w);
    ((float4*)out)[i] = make_float4(0.f, 0.f, 0.f, 0.f);
}

// ---------------- router path ----------------
__global__ void init_kernel() {
    if (threadIdx.x < NE) g_counts[threadIdx.x] = 0;
}

__global__ __launch_bounds__(256) void router_kernel(const float* __restrict__ x,
                                                     const float* __restrict__ gate_w) {
    int warp = (blockIdx.x * blockDim.x + threadIdx.x) >> 5;
    int lane = threadIdx.x & 31;
    if (warp >= NTOK) return;
    const float* xr = x + (size_t)warp * D_MODEL;
    float acc[NE];
#pragma unroll
    for (int e = 0; e < NE; e++) acc[e] = 0.f;
    for (int d = lane; d < D_MODEL; d += 32) {
        float xv = xr[d];
        const float4* gw = (const float4*)(gate_w + (size_t)d * NE);
        float4 a = gw[0], b = gw[1];
        acc[0] = fmaf(xv, a.x, acc[0]); acc[1] = fmaf(xv, a.y, acc[1]);
        acc[2] = fmaf(xv, a.z, acc[2]); acc[3] = fmaf(xv, a.w, acc[3]);
        acc[4] = fmaf(xv, b.x, acc[4]); acc[5] = fmaf(xv, b.y, acc[5]);
        acc[6] = fmaf(xv, b.z, acc[6]); acc[7] = fmaf(xv, b.w, acc[7]);
    }
#pragma unroll
    for (int e = 0; e < NE; e++)
#pragma unroll
        for (int o = 16; o > 0; o >>= 1)
            acc[e] += __shfl_xor_sync(0xffffffffu, acc[e], o);
    if (lane == 0) {
        float mx = acc[0];
#pragma unroll
        for (int e = 1; e < NE; e++) mx = fmaxf(mx, acc[e]);
        float p[NE]; float s = 0.f;
#pragma unroll
        for (int e = 0; e < NE; e++) { p[e] = expf(acc[e] - mx); s += p[e]; }
        float inv = 1.0f / s;
#pragma unroll
        for (int e = 0; e < NE; e++) p[e] *= inv;
        int i0 = 0;
#pragma unroll
        for (int e = 1; e < NE; e++) if (p[e] > p[i0]) i0 = e;
        int i1 = (i0 == 0) ? 1 : 0;
#pragma unroll
        for (int e = 0; e < NE; e++) if (e != i0 && p[e] > p[i1]) i1 = e;
        float w0 = p[i0], w1 = p[i1];
        float isw = 1.0f / (w0 + w1);
        g_expert_of[warp * 2 + 0] = i0;
        g_expert_of[warp * 2 + 1] = i1;
        g_w_of[warp * 2 + 0] = w0 * isw;
        g_w_of[warp * 2 + 1] = w1 * isw;
        atomicAdd(&g_counts[i0], 1);
        atomicAdd(&g_counts[i1], 1);
    }
}

__global__ void setup_kernel() {
    if (threadIdx.x == 0) {
        int off = 0, t = 0;
        for (int e = 0; e < NE; e++) {
            g_cursor[e] = off;
            int nt = (g_counts[e] + BM - 1) / BM;
            for (int i = 0; i < nt; i++) { g_tile_e[t] = e; g_tile_m0[t] = off + i * BM; t++; }
            off += nt * BM;
        }
        g_ntiles = t;
    }
    __syncthreads();
    for (int i = threadIdx.x; i < MAXM; i += blockDim.x) { g_tok[i] = -1; g_wt[i] = 0.f; }
}

__global__ void scatter_kernel() {
    int idx = blockIdx.x * blockDim.x + threadIdx.x;
    if (idx >= NASSIGN) return;
    int e = g_expert_of[idx];
    int slot = atomicAdd(&g_cursor[e], 1);
    g_tok[slot] = idx >> 1;
    g_wt[slot] = g_w_of[idx];
}

// ---------------- grouped GEMM: single-term fp16, register-staged double buffer ----------------
// SPLIT: K-split factor (blockIdx.z); bias added only by z==0 (GEMM2 is pure atomic accum).
template<bool G1, int KTOT, int NWID, int SPLIT>
__global__ __launch_bounds__(256) void moe_gemm(const float* __restrict__ bias,
                                                float* __restrict__ out) {
    int tile = blockIdx.y;
    if (tile >= g_ntiles) return;
    int e  = g_tile_e[tile];
    int m0 = g_tile_m0[tile];
    int n0 = blockIdx.x * BN;
    const __half* Wh = (G1 ? g_w1h : g_w2h) + (size_t)e * KTOT * NWID;

    extern __shared__ char smem[];
    uint32_t sb = smem_u32(smem);
    __shared__ int   s_tok[BM];
    __shared__ float s_wt[BM];

    int tid = threadIdx.x, lane = tid & 31, wid = tid >> 5;
    int wm = wid >> 2, wn = wid & 3;

    if (tid < BM) { s_tok[tid] = g_tok[m0 + tid]; s_wt[tid] = g_wt[m0 + tid]; }
    __syncthreads();

    // copy mapping: A rows ar, ar+64 (4 uint4/row, col aq); B k-rows bk, bk+16 (16 uint4/row, col bq)
    const int aq = tid & 3, ar = tid >> 2;
    const int bq = tid & 15, bk = tid >> 4;

    const char* aHp[2];
    bool av[2];
#pragma unroll
    for (int r = 0; r < 2; r++) {
        int row = ar + 64 * r;
        if (G1) {
            int tok = s_tok[row];
            av[r] = (tok >= 0);
            aHp[r] = (const char*)g_xh + (size_t)(tok < 0 ? 0 : tok) * KTOT * 2;
        } else {
            av[r] = true;
            aHp[r] = (const char*)g_hh + (size_t)(m0 + row) * KTOT * 2;
        }
    }
    const char* bp[2];
#pragma unroll
    for (int r = 0; r < 2; r++)
        bp[r] = (const char*)(Wh + (size_t)(bk + 16 * r) * NWID + n0);

    uint4 pah[2], pb[2];
    const uint4 z4 = make_uint4(0, 0, 0, 0);
    const int NCHL = KTOT / BK / SPLIT;
    const int kc0  = (SPLIT > 1) ? blockIdx.z * NCHL : 0;

    auto load_chunk = [&](int kci) {
        size_t ko = (size_t)(kc0 + kci) * 64 + aq * 16;
#pragma unroll
        for (int r = 0; r < 2; r++)
            pah[r] = av[r] ? *(const uint4*)(aHp[r] + ko) : z4;
        size_t kb = (size_t)(kc0 + kci) * BK * NWID * 2 + bq * 16;
#pragma unroll
        for (int r = 0; r < 2; r++)
            pb[r] = *(const uint4*)(bp[r] + kb);
    };
    auto store_chunk = [&](int buf) {
        uint32_t base = sb + buf * STAGE_SZ;
#pragma unroll
        for (int r = 0; r < 2; r++)
            sts128(base + (uint32_t)(ar + 64 * r) * PA + aq * 16, pah[r]);
#pragma unroll
        for (int r = 0; r < 2; r++)
            sts128(base + ST_B + (uint32_t)(bk + 16 * r) * PB + bq * 16, pb[r]);
    };

    float acc[4][4][4];
#pragma unroll
    for (int i = 0; i < 4; i++)
#pragma unroll
        for (int j = 0; j < 4; j++)
#pragma unroll
            for (int k = 0; k < 4; k++) acc[i][j][k] = 0.f;

    load_chunk(0);
    store_chunk(0);
    __syncthreads();

#pragma unroll 1
    for (int kc = 0; kc < NCHL; kc++) {
        bool more = (kc + 1 < NCHL);
        if (more) load_chunk(kc + 1);

        uint32_t base = sb + (kc & 1) * STAGE_SZ;
#pragma unroll
        for (int kf = 0; kf < 2; kf++) {
            uint32_t ah[4][4], bh[4][2];
#pragma unroll
            for (int mf = 0; mf < 4; mf++) {
                uint32_t arr = wm * 64 + mf * 16 + (lane & 15);
                ldsm4(ah[mf], base + arr * PA + kf * 32 + ((lane >> 4) << 4));
            }
#pragma unroll
            for (int p = 0; p < 2; p++) {
                uint32_t kr = kf * 16 + (lane & 15);
                uint32_t boff = kr * PB + (wn * 32 + p * 16 + ((lane >> 4) << 3)) * 2;
                uint32_t t[4];
                ldsm4t(t, base + ST_B + boff);
                bh[2 * p][0] = t[0]; bh[2 * p][1] = t[1];
                bh[2 * p + 1][0] = t[2]; bh[2 * p + 1][1] = t[3];
            }
#pragma unroll
            for (int mf = 0; mf < 4; mf++)
#pragma unroll
                for (int nf = 0; nf < 4; nf++)
                    mma16816(acc[mf][nf], ah[mf], bh[nf]);
        }
        if (more) store_chunk((kc + 1) & 1);
        __syncthreads();
    }

    // ---- epilogue ----
    int rb = wm * 64 + (lane >> 2);
    int cb = wn * 32 + (lane & 3) * 2;
    const float* be = bias + (size_t)e * NWID + n0;
    bool addb = (SPLIT == 1) || (blockIdx.z == 0);
#pragma unroll
    for (int mf = 0; mf < 4; mf++) {
#pragma unroll
        for (int h = 0; h < 2; h++) {
            int mloc = rb + mf * 16 + h * 8;
            int m = m0 + mloc;
            if (G1) {
                __half2* hrow = (__half2*)(g_hh + (size_t)m * NWID + n0);
#pragma unroll
                for (int nf = 0; nf < 4; nf++) {
                    int c = cb + nf * 8;
                    float2 bb = *(const float2*)(be + c);
                    float v0 = gelu_erf(acc[mf][nf][2 * h + 0] + bb.x);
                    float v1 = gelu_erf(acc[mf][nf][2 * h + 1] + bb.y);
                    hrow[c >> 1] = __floats2half2_rn(v0, v1);
                }
            } else {
                float wt = s_wt[mloc];
                if (wt != 0.f) {
                    int tok = s_tok[mloc];
                    float* orow = out + (size_t)tok * NWID + n0;
#pragma unroll
                    for (int nf = 0; nf < 4; nf++) {
                        int c = cb + nf * 8;
                        float bx = addb ? be[c] : 0.f, by = addb ? be[c + 1] : 0.f;
                        atomicAdd(orow + c,     wt * (acc[mf][nf][2 * h + 0] + bx));
                        atomicAdd(orow + c + 1, wt * (acc[mf][nf][2 * h + 1] + by));
                    }
                }
            }
        }
    }
}

// ---------------- launch ----------------
extern "C" void kernel_launch(void* const* d_in, const int* in_sizes, int n_in,
                              void* d_out, int out_size) {
    const float* x      = (const float*)d_in[0];
    const float* gate_w = (const float*)d_in[1];
    const float* w1     = (const float*)d_in[2];
    const float* b1     = (const float*)d_in[3];
    const float* w2     = (const float*)d_in[4];
    const float* b2     = (const float*)d_in[5];
    float* out = (float*)d_out;

    cudaFuncSetAttribute(moe_gemm<true,  D_MODEL, D_HID, 1>,
                         cudaFuncAttributeMaxDynamicSharedMemorySize, SMEM_DYN);
    cudaFuncSetAttribute(moe_gemm<false, D_HID, D_MODEL, 2>,
                         cudaFuncAttributeMaxDynamicSharedMemorySize, SMEM_DYN);

    const int WN4 = NE * D_MODEL * D_HID / 4;   // 4718592
    init_kernel<<<1, 32>>>();
    router_kernel<<<NTOK / 8, 256>>>(x, gate_w);
    setup_kernel<<<1, 256>>>();
    scatter_kernel<<<NASSIGN / 256, 256>>>();
    convert_x_kernel<<<(NTOK * D_MODEL / 4 + 255) / 256, 256>>>(x, out);
    convert_w_kernel<true ><<<(WN4 + 255) / 256, 256>>>(w1, WN4);
    convert_w_kernel<false><<<(WN4 + 255) / 256, 256>>>(w2, WN4);
    moe_gemm<true,  D_MODEL, D_HID, 1>
        <<<dim3(D_HID / BN, MAXTILES, 1), 256, SMEM_DYN>>>(b1, out);
    moe_gemm<false, D_HID, D_MODEL, 2>
        <<<dim3(D_MODEL / BN, MAXTILES, 2), 256, SMEM_DYN>>>(b2, out);
}